// round 1
// baseline (speedup 1.0000x reference)
#include <cuda_runtime.h>
#include <cuda_bf16.h>

// Shapes (fixed for this problem)
#define BB 4
#define CC 256
#define PP 1024      // 32*32 spatial positions
#define NPAGE 8
#define NK 8192      // NPAGE * PP
#define AA 64
#define KSPLIT 8
#define TQ 16
#define KC 32

// -------- device scratch (no allocation allowed; __device__ globals) --------
__device__ float g_q[BB * PP * AA];                 // [b][p][a]         1 MB
__device__ float g_k[BB * NK * AA];                 // [b][k][a]         8 MB
__device__ float g_v[BB * NK * CC];                 // [b][k][c]        32 MB
__device__ float g_peq[PP * AA];
__device__ float g_pek[PP * AA];
__device__ float g_part[KSPLIT * BB * PP * CC];     // split-K partials 32 MB

// -------- f32x2 helpers (packed fp32, 2x FFMA throughput on Blackwell) ------
#define FMA2(acc, a, b) asm("fma.rn.f32x2 %0, %1, %2, %0;" : "+l"(acc) : "l"(a), "l"(b))
#define SPLAT2(dst, s)  asm("mov.b64 %0, {%1, %1};" : "=l"(dst) : "f"(s))

__device__ __forceinline__ float2 unpack2(unsigned long long v) {
    float2 r;
    asm("mov.b64 {%0, %1}, %2;" : "=f"(r.x), "=f"(r.y) : "l"(v));
    return r;
}

// ============================================================================
// Kernel 1: positional-encoding projections pe_q / pe_k  [1024, 64]
// pe[p][a] = sum_c PE(p,c) * W[a][c] + b[a]
// ============================================================================
__global__ void pe_proj_kernel(const float* __restrict__ Wpx, const float* __restrict__ bpx,
                               const float* __restrict__ Wpy, const float* __restrict__ bpy) {
    int p = blockIdx.x;
    int y = p >> 5, x = p & 31;
    const float* W = blockIdx.y ? Wpy : Wpx;
    const float* bb = blockIdx.y ? bpy : bpx;
    float* outp = blockIdx.y ? g_pek : g_peq;

    __shared__ float pe[CC];
    int c = threadIdx.x;
    {
        int pos = (c < 128) ? y : x;
        int idx = (c < 128) ? c : (c - 128);
        int j = idx >> 1;
        // div[j] = exp(-ln(10000) * 2j / 128) = exp(-ln(10000) * j / 64)
        float ang = (float)pos * expf(-logf(10000.0f) * (float)j / 64.0f);
        pe[c] = (idx & 1) ? cosf(ang) : sinf(ang);
    }
    __syncthreads();
    if (c < AA) {
        float s = 0.0f;
        #pragma unroll 8
        for (int i = 0; i < CC; i++) s += pe[i] * W[c * CC + i];
        outp[p * AA + c] = s + bb[c];
    }
}

// ============================================================================
// Kernel 2: projection GEMM.
//   C[z][m][n] = sum_c A[z][c][m] * W[n][c] + bias[n] (+ extra[m][n])
// mode 0: q (out g_q,  extra g_peq), mode 1: k (g_k, g_pek), mode 2: v (g_v)
// Tiles: BM=64 BN=64 BK=16, 256 threads, 4x4 microtile, f32x2 inner.
// ============================================================================
__global__ __launch_bounds__(256) void proj_kernel(const float* __restrict__ A,
                                                   const float* __restrict__ W,
                                                   const float* __restrict__ bias,
                                                   int N, int mode) {
    __shared__ __align__(16) float As[16][64];
    __shared__ __align__(16) float Bs[16][66];   // pad to 66: conflict-free STS, 8B-aligned rows

    float* C;
    const float* extra;
    if (mode == 0)      { C = g_q; extra = g_peq; }
    else if (mode == 1) { C = g_k; extra = g_pek; }
    else                { C = g_v; extra = nullptr; }

    int z = blockIdx.z;
    A += (size_t)z * CC * PP;
    C += (size_t)z * PP * N;
    int p0 = blockIdx.x * 64, n0 = blockIdx.y * 64;
    int tx = threadIdx.x & 15, ty = threadIdx.x >> 4;

    unsigned long long acc2[4][2];
    #pragma unroll
    for (int i = 0; i < 4; i++)
        #pragma unroll
        for (int j = 0; j < 2; j++) acc2[i][j] = 0ull;

    for (int c0 = 0; c0 < CC; c0 += 16) {
        *(float4*)&As[ty][tx * 4] = *(const float4*)&A[(c0 + ty) * PP + p0 + tx * 4];
        #pragma unroll
        for (int i = 0; i < 4; i++)
            Bs[tx][ty + 16 * i] = W[(n0 + ty + 16 * i) * CC + c0 + tx];
        __syncthreads();

        #pragma unroll
        for (int kk = 0; kk < 16; kk++) {
            float4 a4 = *(const float4*)&As[kk][ty * 4];
            const unsigned long long* brow = (const unsigned long long*)&Bs[kk][0];
            unsigned long long b0 = brow[tx * 2];
            unsigned long long b1 = brow[tx * 2 + 1];
            unsigned long long ax;
            SPLAT2(ax, a4.x); FMA2(acc2[0][0], ax, b0); FMA2(acc2[0][1], ax, b1);
            SPLAT2(ax, a4.y); FMA2(acc2[1][0], ax, b0); FMA2(acc2[1][1], ax, b1);
            SPLAT2(ax, a4.z); FMA2(acc2[2][0], ax, b0); FMA2(acc2[2][1], ax, b1);
            SPLAT2(ax, a4.w); FMA2(acc2[3][0], ax, b0); FMA2(acc2[3][1], ax, b1);
        }
        __syncthreads();
    }

    #pragma unroll
    for (int i = 0; i < 4; i++) {
        int m = p0 + ty * 4 + i;
        #pragma unroll
        for (int jp = 0; jp < 2; jp++) {
            float2 r = unpack2(acc2[i][jp]);
            int n = n0 + tx * 4 + jp * 2;
            float v0 = r.x + bias[n];
            float v1 = r.y + bias[n + 1];
            if (extra) { v0 += extra[m * N + n]; v1 += extra[m * N + n + 1]; }
            C[m * N + n]     = v0;
            C[m * N + n + 1] = v1;
        }
    }
}

// ============================================================================
// Kernel 3: fused attention with batch-axis softmax (split-K over keys).
// Grid (64, 8): x = q-tile of TQ=16 queries, y = key split of 1024 keys.
// For each 32-key chunk: S[b][q][kk] = q.k * scale, then per (q,kk)
// softmax over the 4 batches (exact), then PV outer-product accumulation.
// ============================================================================
__global__ __launch_bounds__(256, 2) void attn_kernel() {
    extern __shared__ float smf[];
    float* P2f = smf;                 // 2048 floats: packed probs [b][q/2][kk] x2
    float* q_s = smf + 2048;          // 4*16*66 = 4224 (rows padded to 66)
    float* k_s = q_s + 4224;          // 4*32*66 = 8448
    float* Ssm = k_s + 8448;          // 4*16*32 = 2048

    const int tid = threadIdx.x;
    const int qbase = blockIdx.x * TQ;
    const int split = blockIdx.y;
    const int kbase0 = split * (NK / KSPLIT);

    // load Q tile (stays resident): q_s[(b*16+q)*66 + a]
    for (int f = tid; f < BB * TQ * AA; f += 256) {
        int a = f & 63, qq = (f >> 6) & 15, b = f >> 10;
        q_s[(b * TQ + qq) * 66 + a] = g_q[((b << 10) + qbase + qq) * AA + a];
    }

    unsigned long long acc[8][4];     // q-pair x batch accumulators (f32x2 over q)
    #pragma unroll
    for (int qp = 0; qp < 8; qp++)
        #pragma unroll
        for (int b = 0; b < BB; b++) acc[qp][b] = 0ull;

    const int c = tid;                // this thread owns out channel c (0..255)
    const unsigned long long* P2u = (const unsigned long long*)P2f;

    for (int kc = 0; kc < (NK / KSPLIT) / KC; kc++) {
        const int kbase = kbase0 + kc * KC;

        // ---- load K chunk: k_s[(b*32+kk)*66 + a] ----
        for (int f4 = tid; f4 < BB * KC * (AA / 4); f4 += 256) {
            int a4 = f4 & 15, kkq = (f4 >> 4) & 31, b = f4 >> 9;
            float4 kv4 = *(const float4*)&g_k[(((b << 13) + kbase + kkq) << 6) + (a4 << 2)];
            float* dst = &k_s[(b * KC + kkq) * 66 + a4 * 4];
            *(float2*)dst       = make_float2(kv4.x, kv4.y);
            *(float2*)(dst + 2) = make_float2(kv4.z, kv4.w);
        }
        __syncthreads();

        // ---- QK: each thread does 8 dot products (f32x2 over A dim) ----
        {
            int b = tid >> 6, q = (tid >> 2) & 15, ks = tid & 3;
            const unsigned long long* qv = (const unsigned long long*)(q_s + (b * TQ + q) * 66);
            #pragma unroll 2
            for (int j = 0; j < 8; j++) {
                int kk = ks + 4 * j;
                const unsigned long long* kv = (const unsigned long long*)(k_s + (b * KC + kk) * 66);
                unsigned long long a2 = 0ull;
                #pragma unroll
                for (int i = 0; i < 32; i++) FMA2(a2, qv[i], kv[i]);
                float2 r = unpack2(a2);
                Ssm[(b * TQ + q) * KC + kk] = (r.x + r.y) * 0.125f;
            }
        }
        __syncthreads();

        // ---- softmax over batch axis (exact, 4-way) ----
        for (int pidx = tid; pidx < TQ * KC; pidx += 256) {
            int q = pidx >> 5, kk = pidx & 31;
            float s0 = Ssm[(0 * TQ + q) * KC + kk];
            float s1 = Ssm[(1 * TQ + q) * KC + kk];
            float s2 = Ssm[(2 * TQ + q) * KC + kk];
            float s3 = Ssm[(3 * TQ + q) * KC + kk];
            float m = fmaxf(fmaxf(s0, s1), fmaxf(s2, s3));
            float e0 = __expf(s0 - m), e1 = __expf(s1 - m);
            float e2 = __expf(s2 - m), e3 = __expf(s3 - m);
            float r = 1.0f / (e0 + e1 + e2 + e3);
            int base = (q >> 1) * (KC * 2) + kk * 2 + (q & 1);   // within a batch plane
            P2f[0 * 512 + base] = e0 * r;
            P2f[1 * 512 + base] = e1 * r;
            P2f[2 * 512 + base] = e2 * r;
            P2f[3 * 512 + base] = e3 * r;
        }
        __syncthreads();

        // ---- PV: rank-1 accumulation, thread owns channel c ----
        const float* vp0 = &g_v[(size_t)(0 * NK + kbase) * CC + c];
        const float* vp1 = &g_v[(size_t)(1 * NK + kbase) * CC + c];
        const float* vp2 = &g_v[(size_t)(2 * NK + kbase) * CC + c];
        const float* vp3 = &g_v[(size_t)(3 * NK + kbase) * CC + c];
        #pragma unroll 4
        for (int kk = 0; kk < KC; kk++) {
            float v0 = vp0[kk * CC], v1 = vp1[kk * CC], v2 = vp2[kk * CC], v3 = vp3[kk * CC];
            unsigned long long vv0, vv1, vv2, vv3;
            SPLAT2(vv0, v0); SPLAT2(vv1, v1); SPLAT2(vv2, v2); SPLAT2(vv3, v3);
            #pragma unroll
            for (int qp = 0; qp < 8; qp++) {
                FMA2(acc[qp][0], P2u[(0 * 8 + qp) * KC + kk], vv0);
                FMA2(acc[qp][1], P2u[(1 * 8 + qp) * KC + kk], vv1);
                FMA2(acc[qp][2], P2u[(2 * 8 + qp) * KC + kk], vv2);
                FMA2(acc[qp][3], P2u[(3 * 8 + qp) * KC + kk], vv3);
            }
        }
        __syncthreads();   // protect Ssm/P2f/k_s for next chunk
    }

    // ---- write split partials (deterministic; no atomics) ----
    float* part = g_part + (size_t)split * (BB * PP * CC);
    #pragma unroll
    for (int qp = 0; qp < 8; qp++)
        #pragma unroll
        for (int b = 0; b < BB; b++) {
            float2 r = unpack2(acc[qp][b]);
            size_t base = ((size_t)(b << 10) + qbase + 2 * qp) * CC + c;
            part[base]       = r.x;
            part[base + CC]  = r.y;
        }
}

// ============================================================================
// Kernel 4: split-K reduction into d_out ([B][q][c] flat == [B][256][32][32])
// ============================================================================
__global__ void reduce_kernel(float* __restrict__ out) {
    int i = blockIdx.x * blockDim.x + threadIdx.x;   // 262144 float4s
    const float4* p = (const float4*)g_part;
    float4 s = p[i];
    #pragma unroll
    for (int sp = 1; sp < KSPLIT; sp++) {
        float4 t = p[(size_t)sp * (BB * PP * CC / 4) + i];
        s.x += t.x; s.y += t.y; s.z += t.z; s.w += t.w;
    }
    ((float4*)out)[i] = s;
}

// ============================================================================
extern "C" void kernel_launch(void* const* d_in, const int* in_sizes, int n_in,
                              void* d_out, int out_size) {
    const float* zx  = (const float*)d_in[0];
    const float* zy  = (const float*)d_in[1];
    const float* Wq  = (const float*)d_in[2];
    const float* bq  = (const float*)d_in[3];
    const float* Wpx = (const float*)d_in[4];
    const float* bpx = (const float*)d_in[5];
    const float* Wk  = (const float*)d_in[6];
    const float* bk  = (const float*)d_in[7];
    const float* Wpy = (const float*)d_in[8];
    const float* bpy = (const float*)d_in[9];
    const float* Wv  = (const float*)d_in[10];
    const float* bv  = (const float*)d_in[11];
    float* out = (float*)d_out;

    const int attn_smem = (2048 + 4224 + 8448 + 2048) * 4;   // 67072 B
    cudaFuncSetAttribute(attn_kernel, cudaFuncAttributeMaxDynamicSharedMemorySize, attn_smem);

    pe_proj_kernel<<<dim3(PP, 2), CC>>>(Wpx, bpx, Wpy, bpy);
    proj_kernel<<<dim3(16, 1, 4),  256>>>(zx, Wq, bq, 64, 0);    // q
    proj_kernel<<<dim3(16, 1, 32), 256>>>(zy, Wk, bk, 64, 1);    // k
    proj_kernel<<<dim3(16, 4, 32), 256>>>(zy, Wv, bv, 256, 2);   // v
    attn_kernel<<<dim3(PP / TQ, KSPLIT), 256, attn_smem>>>();
    reduce_kernel<<<(BB * PP * CC / 4) / 256, 256>>>(out);
}

// round 2
// speedup vs baseline: 3.3173x; 3.3173x over previous
#include <cuda_runtime.h>
#include <cuda_bf16.h>
#include <cstdint>

// Fixed shapes
#define BB 4
#define CC 256
#define PP 1024
#define NK 8192
#define AA 64
#define PL (PP * NK)          // 8388608 floats per batch plane of S
#define PVSPLIT 4

// -------- device scratch --------
__device__ float g_q[BB * PP * AA];                   //  1 MB
__device__ float g_k[BB * NK * AA];                   //  8 MB
__device__ float g_v[BB * NK * CC];                   // 32 MB
__device__ float g_peq[PP * AA];
__device__ float g_pek[PP * AA];
__device__ float g_S[(size_t)BB * PL];                // 128 MB (S, then P in place)
__device__ float g_part[PVSPLIT * BB * PP * CC];      // 16 MB split-K partials

// -------- helpers --------
__device__ __forceinline__ uint32_t f2tf(float f) {
    uint32_t r;
    asm("cvt.rna.tf32.f32 %0, %1;" : "=r"(r) : "f"(f));
    return r;
}

__device__ __forceinline__ void mma8(float* c, const uint32_t* a, const uint32_t* b) {
    asm volatile("mma.sync.aligned.m16n8k8.row.col.f32.tf32.tf32.f32 "
                 "{%0,%1,%2,%3}, {%4,%5,%6,%7}, {%8,%9}, {%0,%1,%2,%3};"
                 : "+f"(c[0]), "+f"(c[1]), "+f"(c[2]), "+f"(c[3])
                 : "r"(a[0]), "r"(a[1]), "r"(a[2]), "r"(a[3]), "r"(b[0]), "r"(b[1]));
}

__device__ __forceinline__ uint4 cvt4(float4 v) {
    uint4 r;
    r.x = f2tf(v.x); r.y = f2tf(v.y); r.z = f2tf(v.z); r.w = f2tf(v.w);
    return r;
}

// ============================================================================
// Kernel 1: positional-encoding projections pe_q / pe_k  [1024, 64]
// ============================================================================
__global__ void pe_proj_kernel(const float* __restrict__ Wpx, const float* __restrict__ bpx,
                               const float* __restrict__ Wpy, const float* __restrict__ bpy) {
    int p = blockIdx.x;
    int y = p >> 5, x = p & 31;
    const float* W = blockIdx.y ? Wpy : Wpx;
    const float* bb = blockIdx.y ? bpy : bpx;
    float* outp = blockIdx.y ? g_pek : g_peq;

    __shared__ float pe[CC];
    int c = threadIdx.x;
    {
        int pos = (c < 128) ? y : x;
        int idx = (c < 128) ? c : (c - 128);
        int j = idx >> 1;
        float ang = (float)pos * expf(-logf(10000.0f) * (float)j / 64.0f);
        pe[c] = (idx & 1) ? cosf(ang) : sinf(ang);
    }
    __syncthreads();
    if (c < AA) {
        float s = 0.0f;
        #pragma unroll 8
        for (int i = 0; i < CC; i++) s += pe[i] * W[c * CC + i];
        outp[p * AA + c] = s + bb[c];
    }
}

// ============================================================================
// Kernel 2: tf32 projection GEMM.
//   C[z][m][n] = sum_c A[z][c][m] * W[n][c] + bias[n] (+ extra[m][n])
// BM=128, BN=64, BK=32. 256 threads = 8 warps in 4x2 (m x n).
// modes: 0 -> g_q (+g_peq), 1 -> g_k (+g_pek), 2 -> g_v
// ============================================================================
__global__ __launch_bounds__(256) void proj_mma(const float* __restrict__ A,
                                                const float* __restrict__ W,
                                                const float* __restrict__ bias,
                                                int N, int mode) {
    __shared__ uint32_t As[32][136];   // [k][m], 136%32==8 -> conflict-free frag loads
    __shared__ uint32_t Ws[64][36];    // [n][k], 36%32==4  -> conflict-free

    float* C;
    const float* extra;
    if (mode == 0)      { C = g_q; extra = g_peq; }
    else if (mode == 1) { C = g_k; extra = g_pek; }
    else                { C = g_v; extra = nullptr; }

    int z = blockIdx.z;
    A += (size_t)z * CC * PP;
    C += (size_t)z * PP * N;
    int m0 = blockIdx.x * 128, n0 = blockIdx.y * 64;

    int tid = threadIdx.x;
    int wid = tid >> 5;
    int g = (tid >> 2) & 7, tg = tid & 3;
    int mbase = (wid >> 1) * 32;        // warp m-offset (4 warps over m)
    int nbase = (wid & 1) * 32;         // warp n-offset (2 warps over n)

    float acc[2][4][4];
    #pragma unroll
    for (int i = 0; i < 2; i++)
        #pragma unroll
        for (int j = 0; j < 4; j++)
            #pragma unroll
            for (int r = 0; r < 4; r++) acc[i][j][r] = 0.0f;

    for (int c0 = 0; c0 < CC; c0 += 32) {
        // load A tile [32 k][128 m]
        #pragma unroll
        for (int i = 0; i < 4; i++) {
            int idx = i * 256 + tid;
            int row = idx >> 5, c4 = idx & 31;
            float4 v = *(const float4*)&A[(size_t)(c0 + row) * PP + m0 + c4 * 4];
            *(uint4*)&As[row][c4 * 4] = cvt4(v);
        }
        // load W tile [64 n][32 k]
        #pragma unroll
        for (int i = 0; i < 2; i++) {
            int idx = i * 256 + tid;
            int row = idx >> 3, c4 = idx & 7;
            float4 v = *(const float4*)&W[(size_t)(n0 + row) * CC + c0 + c4 * 4];
            *(uint4*)&Ws[row][c4 * 4] = cvt4(v);
        }
        __syncthreads();

        #pragma unroll
        for (int ks = 0; ks < 4; ks++) {
            int k0 = ks * 8;
            uint32_t af[2][4], bf[4][2];
            #pragma unroll
            for (int mt = 0; mt < 2; mt++) {
                int mr = mbase + mt * 16;
                af[mt][0] = As[k0 + tg][mr + g];
                af[mt][1] = As[k0 + tg][mr + g + 8];
                af[mt][2] = As[k0 + tg + 4][mr + g];
                af[mt][3] = As[k0 + tg + 4][mr + g + 8];
            }
            #pragma unroll
            for (int nt = 0; nt < 4; nt++) {
                int nr = nbase + nt * 8;
                bf[nt][0] = Ws[nr + g][k0 + tg];
                bf[nt][1] = Ws[nr + g][k0 + tg + 4];
            }
            #pragma unroll
            for (int mt = 0; mt < 2; mt++)
                #pragma unroll
                for (int nt = 0; nt < 4; nt++)
                    mma8(acc[mt][nt], af[mt], bf[nt]);
        }
        __syncthreads();
    }

    // epilogue
    #pragma unroll
    for (int mt = 0; mt < 2; mt++) {
        int r0 = m0 + mbase + mt * 16 + g;
        #pragma unroll
        for (int nt = 0; nt < 4; nt++) {
            int col = n0 + nbase + nt * 8 + 2 * tg;
            float b0 = bias[col], b1 = bias[col + 1];
            float e00 = 0, e01 = 0, e10 = 0, e11 = 0;
            if (mode < 2) {
                e00 = extra[(r0)     * AA + col]; e01 = extra[(r0)     * AA + col + 1];
                e10 = extra[(r0 + 8) * AA + col]; e11 = extra[(r0 + 8) * AA + col + 1];
            }
            *(float2*)&C[(size_t)r0 * N + col] =
                make_float2(acc[mt][nt][0] + b0 + e00, acc[mt][nt][1] + b1 + e01);
            *(float2*)&C[(size_t)(r0 + 8) * N + col] =
                make_float2(acc[mt][nt][2] + b0 + e10, acc[mt][nt][3] + b1 + e11);
        }
    }
}

// ============================================================================
// Kernel 3: S = scale * Q @ K^T   [b][1024][8192], tf32 mma, K=64 resident.
// BM=128, BN=128. 8 warps in 2x4 (m x n). grid (8, 64, 4).
// ============================================================================
__global__ __launch_bounds__(256) void qk_mma() {
    extern __shared__ uint32_t sm[];
    uint32_t (*Qs)[68] = (uint32_t(*)[68])sm;            // [128 m][64 k] pad 68
    uint32_t (*Ks)[68] = (uint32_t(*)[68])(sm + 128 * 68);

    int b = blockIdx.z;
    int m0 = blockIdx.x * 128, n0 = blockIdx.y * 128;
    int tid = threadIdx.x;
    int wid = tid >> 5;
    int g = (tid >> 2) & 7, tg = tid & 3;
    int mbase = (wid >> 2) * 64;
    int nbase = (wid & 3) * 32;

    // load Q and K tiles (full K=64)
    #pragma unroll
    for (int i = 0; i < 8; i++) {
        int idx = i * 256 + tid;
        int row = idx >> 4, c4 = idx & 15;
        float4 q = *(const float4*)&g_q[(size_t)((b << 10) + m0 + row) * AA + c4 * 4];
        *(uint4*)&Qs[row][c4 * 4] = cvt4(q);
        float4 k = *(const float4*)&g_k[(size_t)((b << 13) + n0 + row) * AA + c4 * 4];
        *(uint4*)&Ks[row][c4 * 4] = cvt4(k);
    }
    __syncthreads();

    float acc[4][4][4];
    #pragma unroll
    for (int i = 0; i < 4; i++)
        #pragma unroll
        for (int j = 0; j < 4; j++)
            #pragma unroll
            for (int r = 0; r < 4; r++) acc[i][j][r] = 0.0f;

    #pragma unroll
    for (int ks = 0; ks < 8; ks++) {
        int k0 = ks * 8;
        uint32_t af[4][4], bf[4][2];
        #pragma unroll
        for (int mt = 0; mt < 4; mt++) {
            int mr = mbase + mt * 16;
            af[mt][0] = Qs[mr + g][k0 + tg];
            af[mt][1] = Qs[mr + g + 8][k0 + tg];
            af[mt][2] = Qs[mr + g][k0 + tg + 4];
            af[mt][3] = Qs[mr + g + 8][k0 + tg + 4];
        }
        #pragma unroll
        for (int nt = 0; nt < 4; nt++) {
            int nr = nbase + nt * 8;
            bf[nt][0] = Ks[nr + g][k0 + tg];
            bf[nt][1] = Ks[nr + g][k0 + tg + 4];
        }
        #pragma unroll
        for (int mt = 0; mt < 4; mt++)
            #pragma unroll
            for (int nt = 0; nt < 4; nt++)
                mma8(acc[mt][nt], af[mt], bf[nt]);
    }

    float* S = g_S + (size_t)b * PL;
    #pragma unroll
    for (int mt = 0; mt < 4; mt++) {
        int r0 = m0 + mbase + mt * 16 + g;
        #pragma unroll
        for (int nt = 0; nt < 4; nt++) {
            int col = n0 + nbase + nt * 8 + 2 * tg;
            *(float2*)&S[(size_t)r0 * NK + col] =
                make_float2(acc[mt][nt][0] * 0.125f, acc[mt][nt][1] * 0.125f);
            *(float2*)&S[(size_t)(r0 + 8) * NK + col] =
                make_float2(acc[mt][nt][2] * 0.125f, acc[mt][nt][3] * 0.125f);
        }
    }
}

// ============================================================================
// Kernel 4: softmax over the batch axis, in place on g_S. Pure streaming.
// ============================================================================
__global__ void softmax_b() {
    size_t i = (size_t)blockIdx.x * 256 + threadIdx.x;   // float4 index
    float4* p0 = (float4*)g_S + i;
    float4* p1 = (float4*)(g_S + PL) + i;
    float4* p2 = (float4*)(g_S + 2 * (size_t)PL) + i;
    float4* p3 = (float4*)(g_S + 3 * (size_t)PL) + i;
    float4 s0 = *p0, s1 = *p1, s2 = *p2, s3 = *p3;
    #pragma unroll
    for (int l = 0; l < 4; l++) {
        float a0 = ((float*)&s0)[l], a1 = ((float*)&s1)[l];
        float a2 = ((float*)&s2)[l], a3 = ((float*)&s3)[l];
        float m = fmaxf(fmaxf(a0, a1), fmaxf(a2, a3));
        float e0 = __expf(a0 - m), e1 = __expf(a1 - m);
        float e2 = __expf(a2 - m), e3 = __expf(a3 - m);
        float r = 1.0f / (e0 + e1 + e2 + e3);
        ((float*)&s0)[l] = e0 * r; ((float*)&s1)[l] = e1 * r;
        ((float*)&s2)[l] = e2 * r; ((float*)&s3)[l] = e3 * r;
    }
    *p0 = s0; *p1 = s1; *p2 = s2; *p3 = s3;
}

// ============================================================================
// Kernel 5: O = P @ V, split-K=4 over the 8192 keys.
// BM=128, BN=128, BK=64. 8 warps in 4x2 (m x n). grid (8, 2, 16).
// ============================================================================
__global__ __launch_bounds__(256) void pv_mma() {
    extern __shared__ uint32_t sm[];
    uint32_t (*Ps)[68]  = (uint32_t(*)[68])sm;            // [128 m][64 k]
    uint32_t (*Vs)[136] = (uint32_t(*)[136])(sm + 128 * 68);  // [64 k][128 n]

    int b = blockIdx.z >> 2;
    int split = blockIdx.z & 3;
    int m0 = blockIdx.x * 128, n0 = blockIdx.y * 128;
    int tid = threadIdx.x;
    int wid = tid >> 5;
    int g = (tid >> 2) & 7, tg = tid & 3;
    int mbase = (wid >> 1) * 32;   // 4 warps over m
    int nbase = (wid & 1) * 64;    // 2 warps over n

    const float* P = g_S + (size_t)b * PL;
    const float* V = g_v + (size_t)b * NK * CC;

    float acc[2][8][4];
    #pragma unroll
    for (int i = 0; i < 2; i++)
        #pragma unroll
        for (int j = 0; j < 8; j++)
            #pragma unroll
            for (int r = 0; r < 4; r++) acc[i][j][r] = 0.0f;

    int kstart = split * (NK / PVSPLIT);
    for (int kc = 0; kc < (NK / PVSPLIT) / 64; kc++) {
        int kb = kstart + kc * 64;
        // load P tile [128 m][64 k]
        #pragma unroll
        for (int i = 0; i < 8; i++) {
            int idx = i * 256 + tid;
            int row = idx >> 4, c4 = idx & 15;
            float4 v = *(const float4*)&P[(size_t)(m0 + row) * NK + kb + c4 * 4];
            *(uint4*)&Ps[row][c4 * 4] = cvt4(v);
        }
        // load V tile [64 k][128 n]
        #pragma unroll
        for (int i = 0; i < 8; i++) {
            int idx = i * 256 + tid;
            int row = idx >> 5, c4 = idx & 31;
            float4 v = *(const float4*)&V[(size_t)(kb + row) * CC + n0 + c4 * 4];
            *(uint4*)&Vs[row][c4 * 4] = cvt4(v);
        }
        __syncthreads();

        #pragma unroll
        for (int ks = 0; ks < 8; ks++) {
            int k0 = ks * 8;
            uint32_t af[2][4], bf[8][2];
            #pragma unroll
            for (int mt = 0; mt < 2; mt++) {
                int mr = mbase + mt * 16;
                af[mt][0] = Ps[mr + g][k0 + tg];
                af[mt][1] = Ps[mr + g + 8][k0 + tg];
                af[mt][2] = Ps[mr + g][k0 + tg + 4];
                af[mt][3] = Ps[mr + g + 8][k0 + tg + 4];
            }
            #pragma unroll
            for (int nt = 0; nt < 8; nt++) {
                int nr = nbase + nt * 8;
                bf[nt][0] = Vs[k0 + tg][nr + g];
                bf[nt][1] = Vs[k0 + tg + 4][nr + g];
            }
            #pragma unroll
            for (int mt = 0; mt < 2; mt++)
                #pragma unroll
                for (int nt = 0; nt < 8; nt++)
                    mma8(acc[mt][nt], af[mt], bf[nt]);
        }
        __syncthreads();
    }

    float* part = g_part + (size_t)split * (BB * PP * CC);
    #pragma unroll
    for (int mt = 0; mt < 2; mt++) {
        int r0 = m0 + mbase + mt * 16 + g;
        #pragma unroll
        for (int nt = 0; nt < 8; nt++) {
            int col = n0 + nbase + nt * 8 + 2 * tg;
            *(float2*)&part[(size_t)((b << 10) + r0) * CC + col] =
                make_float2(acc[mt][nt][0], acc[mt][nt][1]);
            *(float2*)&part[(size_t)((b << 10) + r0 + 8) * CC + col] =
                make_float2(acc[mt][nt][2], acc[mt][nt][3]);
        }
    }
}

// ============================================================================
// Kernel 6: deterministic 4-way split-K reduction into d_out ([b][p][c])
// ============================================================================
__global__ void reduce4(float* __restrict__ out) {
    int i = blockIdx.x * blockDim.x + threadIdx.x;   // 262144 float4s
    const float4* p = (const float4*)g_part;
    const int plane = BB * PP * CC / 4;
    float4 s = p[i];
    #pragma unroll
    for (int sp = 1; sp < PVSPLIT; sp++) {
        float4 t = p[(size_t)sp * plane + i];
        s.x += t.x; s.y += t.y; s.z += t.z; s.w += t.w;
    }
    ((float4*)out)[i] = s;
}

// ============================================================================
extern "C" void kernel_launch(void* const* d_in, const int* in_sizes, int n_in,
                              void* d_out, int out_size) {
    const float* zx  = (const float*)d_in[0];
    const float* zy  = (const float*)d_in[1];
    const float* Wq  = (const float*)d_in[2];
    const float* bq  = (const float*)d_in[3];
    const float* Wpx = (const float*)d_in[4];
    const float* bpx = (const float*)d_in[5];
    const float* Wk  = (const float*)d_in[6];
    const float* bk  = (const float*)d_in[7];
    const float* Wpy = (const float*)d_in[8];
    const float* bpy = (const float*)d_in[9];
    const float* Wv  = (const float*)d_in[10];
    const float* bv  = (const float*)d_in[11];
    float* out = (float*)d_out;

    const int qk_smem = 2 * 128 * 68 * 4;              // 69632 B
    const int pv_smem = (128 * 68 + 64 * 136) * 4;     // 69632 B
    cudaFuncSetAttribute(qk_mma, cudaFuncAttributeMaxDynamicSharedMemorySize, qk_smem);
    cudaFuncSetAttribute(pv_mma, cudaFuncAttributeMaxDynamicSharedMemorySize, pv_smem);

    pe_proj_kernel<<<dim3(PP, 2), CC>>>(Wpx, bpx, Wpy, bpy);
    proj_mma<<<dim3(8, 1, 4),  256>>>(zx, Wq, bq, 64, 0);    // q
    proj_mma<<<dim3(8, 1, 32), 256>>>(zy, Wk, bk, 64, 1);    // k
    proj_mma<<<dim3(8, 4, 32), 256>>>(zy, Wv, bv, 256, 2);   // v
    qk_mma<<<dim3(8, 64, 4), 256, qk_smem>>>();
    softmax_b<<<(BB * PL / 4) / (BB * 256), 256>>>();        // 8192 blocks
    pv_mma<<<dim3(8, 2, 16), 256, pv_smem>>>();
    reduce4<<<(BB * PP * CC / 4) / 256, 256>>>(out);
}